// round 1
// baseline (speedup 1.0000x reference)
#include <cuda_runtime.h>
#include <cuda_bf16.h>

#define NROWS 8192
#define DIM   128
#define MARGIN 0.2f

#define BM 128
#define BN 128
#define PAD 132          // row stride in floats; 132*4=528 bytes, 16B aligned per k-row
#define NTILES 64        // 8192/128
#define SMEM_BYTES (2 * DIM * PAD * 4)

// Scratch (no allocations allowed in kernel_launch)
__device__ float g_a[NROWS];            // yy[i] - 2*<x_i,y_i> + margin
__device__ float g_b[NROWS];            // yy[j]
__device__ float g_part[NTILES * NTILES];

// ---------------------------------------------------------------------------
// Precompute a[i], b[i]. One warp per row; each lane loads one float4 (4 elems).
// ---------------------------------------------------------------------------
__global__ void precompute_kernel(const float* __restrict__ x,
                                  const float* __restrict__ y) {
    int row  = blockIdx.x * 8 + (threadIdx.x >> 5);
    int lane = threadIdx.x & 31;

    float4 xv = reinterpret_cast<const float4*>(x + (size_t)row * DIM)[lane];
    float4 yv = reinterpret_cast<const float4*>(y + (size_t)row * DIM)[lane];

    float yy  = yv.x * yv.x + yv.y * yv.y + yv.z * yv.z + yv.w * yv.w;
    float dxy = xv.x * yv.x + xv.y * yv.y + xv.z * yv.z + xv.w * yv.w;

    #pragma unroll
    for (int off = 16; off > 0; off >>= 1) {
        yy  += __shfl_xor_sync(0xFFFFFFFFu, yy,  off);
        dxy += __shfl_xor_sync(0xFFFFFFFFu, dxy, off);
    }
    if (lane == 0) {
        g_b[row] = yy;
        g_a[row] = yy - 2.0f * dxy + MARGIN;
    }
}

// ---------------------------------------------------------------------------
// Fused tile kernel: S-tile = x_tile @ y_tile^T, epilogue relu-sum in-place.
// Grid (64, 64); block 256 threads; each thread owns an 8x8 microtile.
// smem layout is k-major: xs[k*PAD + m], ys[k*PAD + n].
// ---------------------------------------------------------------------------
__global__ void __launch_bounds__(256, 1)
tile_kernel(const float* __restrict__ x, const float* __restrict__ y) {
    extern __shared__ float smem[];
    float* xs = smem;
    float* ys = smem + DIM * PAD;

    const int gm0 = blockIdx.y * BM;
    const int gn0 = blockIdx.x * BN;
    const int tid = threadIdx.x;

    // Load both 128x128 tiles, transposing to k-major.
    // 4096 float4 per tile / 256 threads = 16 per thread.
    #pragma unroll
    for (int it = 0; it < 16; it++) {
        int f  = tid + it * 256;          // float4 index in tile
        int r  = f >> 5;                  // row within tile (32 float4 per row)
        int c4 = f & 31;
        int k  = c4 * 4;

        float4 v = reinterpret_cast<const float4*>(x + (size_t)(gm0 + r) * DIM)[c4];
        xs[(k + 0) * PAD + r] = v.x;
        xs[(k + 1) * PAD + r] = v.y;
        xs[(k + 2) * PAD + r] = v.z;
        xs[(k + 3) * PAD + r] = v.w;

        float4 w = reinterpret_cast<const float4*>(y + (size_t)(gn0 + r) * DIM)[c4];
        ys[(k + 0) * PAD + r] = w.x;
        ys[(k + 1) * PAD + r] = w.y;
        ys[(k + 2) * PAD + r] = w.z;
        ys[(k + 3) * PAD + r] = w.w;
    }
    __syncthreads();

    const int ty = tid >> 4;   // 0..15 -> m block
    const int tx = tid & 15;   // 0..15 -> n block

    float acc[8][8];
    #pragma unroll
    for (int i = 0; i < 8; i++)
        #pragma unroll
        for (int j = 0; j < 8; j++) acc[i][j] = 0.0f;

    #pragma unroll 4
    for (int k = 0; k < DIM; k++) {
        float4 m0 = *reinterpret_cast<const float4*>(&xs[k * PAD + ty * 8]);
        float4 m1 = *reinterpret_cast<const float4*>(&xs[k * PAD + ty * 8 + 4]);
        float4 n0 = *reinterpret_cast<const float4*>(&ys[k * PAD + tx * 8]);
        float4 n1 = *reinterpret_cast<const float4*>(&ys[k * PAD + tx * 8 + 4]);
        float rm[8] = {m0.x, m0.y, m0.z, m0.w, m1.x, m1.y, m1.z, m1.w};
        float rn[8] = {n0.x, n0.y, n0.z, n0.w, n1.x, n1.y, n1.z, n1.w};
        #pragma unroll
        for (int i = 0; i < 8; i++)
            #pragma unroll
            for (int j = 0; j < 8; j++)
                acc[i][j] = fmaf(rm[i], rn[j], acc[i][j]);
    }

    // Fused epilogue: v = a[i] + 2*S - b[j]; skip diagonal; relu-sum.
    float s = 0.0f;
    #pragma unroll
    for (int mi = 0; mi < 8; mi++) {
        int   gi = gm0 + ty * 8 + mi;
        float ai = g_a[gi];
        #pragma unroll
        for (int ni = 0; ni < 8; ni++) {
            int   gj = gn0 + tx * 8 + ni;
            float v  = fmaf(2.0f, acc[mi][ni], ai - g_b[gj]);
            if (gi != gj && v > 0.0f) s += v;
        }
    }

    // Block reduction (deterministic).
    #pragma unroll
    for (int off = 16; off > 0; off >>= 1)
        s += __shfl_xor_sync(0xFFFFFFFFu, s, off);

    __shared__ float wsum[8];
    if ((tid & 31) == 0) wsum[tid >> 5] = s;
    __syncthreads();
    if (tid == 0) {
        float t = 0.0f;
        #pragma unroll
        for (int w = 0; w < 8; w++) t += wsum[w];
        g_part[blockIdx.y * NTILES + blockIdx.x] = t;
    }
}

// ---------------------------------------------------------------------------
// Final reduction: 4096 partials -> mean. Single block, deterministic.
// ---------------------------------------------------------------------------
__global__ void reduce_kernel(float* __restrict__ out) {
    __shared__ double sh[32];
    int tid = threadIdx.x;   // 1024 threads

    double s = (double)g_part[tid] + (double)g_part[tid + 1024] +
               (double)g_part[tid + 2048] + (double)g_part[tid + 3072];

    #pragma unroll
    for (int off = 16; off > 0; off >>= 1)
        s += __shfl_xor_sync(0xFFFFFFFFu, s, off);
    if ((tid & 31) == 0) sh[tid >> 5] = s;
    __syncthreads();
    if (tid == 0) {
        double t = 0.0;
        #pragma unroll
        for (int w = 0; w < 32; w++) t += sh[w];
        out[0] = (float)(t / ((double)NROWS * (double)NROWS));
    }
}

// ---------------------------------------------------------------------------
extern "C" void kernel_launch(void* const* d_in, const int* in_sizes, int n_in,
                              void* d_out, int out_size) {
    const float* x = (const float*)d_in[0];
    const float* y = (const float*)d_in[1];
    float* out = (float*)d_out;

    cudaFuncSetAttribute(tile_kernel,
                         cudaFuncAttributeMaxDynamicSharedMemorySize, SMEM_BYTES);

    precompute_kernel<<<NROWS / 8, 256>>>(x, y);
    tile_kernel<<<dim3(NTILES, NTILES), 256, SMEM_BYTES>>>(x, y);
    reduce_kernel<<<1, 1024>>>(out);
}